// round 6
// baseline (speedup 1.0000x reference)
#include <cuda_runtime.h>

#define NUM_CLASSES 1000
#define FEAT_DIM    256
#define NROWS       262144
#define NBLK        256          // chunks for hierarchical counting sort

// Device-global scratch (no allocation allowed in kernel_launch).
__device__ int g_hist[NBLK * NUM_CLASSES];   // per-block hist -> per-block excl prefix
__device__ int g_count[NUM_CLASSES];
__device__ int g_offset[NUM_CLASSES];
__device__ int g_idx[NROWS];

// ---------------------------------------------------------------------------
// Kernel 1: per-block label histogram (smem privatized, int4 label loads)
// ---------------------------------------------------------------------------
__global__ void k_hist(const int* __restrict__ labels, int n, int rpb) {
    __shared__ int h[NUM_CLASSES];
    for (int i = threadIdx.x; i < NUM_CLASSES; i += blockDim.x) h[i] = 0;
    __syncthreads();
    int base = blockIdx.x * rpb;
    int q    = rpb >> 2;
    const int4* lab4 = (const int4*)(labels + base);   // base % 4 == 0
    for (int j4 = threadIdx.x; j4 < q; j4 += blockDim.x) {
        int r = base + (j4 << 2);
        if (r + 3 < n) {
            int4 L = lab4[j4];
            atomicAdd(&h[L.x], 1);
            atomicAdd(&h[L.y], 1);
            atomicAdd(&h[L.z], 1);
            atomicAdd(&h[L.w], 1);
        } else {
            for (int k = 0; k < 4; k++)
                if (r + k < n) atomicAdd(&h[labels[r + k]], 1);
        }
    }
    __syncthreads();
    int* dst = &g_hist[blockIdx.x * NUM_CLASSES];
    for (int i = threadIdx.x; i < NUM_CLASSES; i += blockDim.x) dst[i] = h[i];
}

// ---------------------------------------------------------------------------
// Kernel 2: per-class exclusive scan across the NBLK block-chunks.
// ---------------------------------------------------------------------------
__global__ void k_scanA() {
    int c = blockIdx.x;
    int t = threadIdx.x;
    int v = g_hist[t * NUM_CLASSES + c];

    int lane = t & 31, w = t >> 5;
    int x = v;
    #pragma unroll
    for (int o = 1; o < 32; o <<= 1) {
        int y = __shfl_up_sync(0xffffffffu, x, o);
        if (lane >= o) x += y;
    }
    __shared__ int wt[NBLK / 32];
    if (lane == 31) wt[w] = x;
    __syncthreads();
    if (t == 0) {
        int s = 0;
        #pragma unroll
        for (int i = 0; i < NBLK / 32; i++) { int tmp = wt[i]; wt[i] = s; s += tmp; }
    }
    __syncthreads();
    int incl = x + wt[w];
    g_hist[t * NUM_CLASSES + c] = incl - v;   // exclusive prefix within class
    if (t == NBLK - 1) g_count[c] = incl;     // class total
}

// ---------------------------------------------------------------------------
// Kernel 3: exclusive scan over 1000 class totals (single block)
// ---------------------------------------------------------------------------
__global__ void k_scanB() {
    __shared__ int s[1024];
    int t = threadIdx.x;
    s[t] = (t < NUM_CLASSES) ? g_count[t] : 0;
    for (int off = 1; off < 1024; off <<= 1) {
        __syncthreads();
        int v = (t >= off) ? s[t - off] : 0;
        __syncthreads();
        s[t] += v;
    }
    __syncthreads();
    if (t < NUM_CLASSES) g_offset[t] = (t == 0) ? 0 : s[t - 1];
}

// ---------------------------------------------------------------------------
// Kernel 4: scatter row indices; smem cursors only, int4 label loads.
// ---------------------------------------------------------------------------
__global__ void k_scatter(const int* __restrict__ labels, int n, int rpb) {
    __shared__ int cursor[NUM_CLASSES];
    int b = blockIdx.x;
    const int* pre = &g_hist[b * NUM_CLASSES];
    for (int c = threadIdx.x; c < NUM_CLASSES; c += blockDim.x)
        cursor[c] = g_offset[c] + pre[c];
    __syncthreads();
    int base = b * rpb;
    int q    = rpb >> 2;
    const int4* lab4 = (const int4*)(labels + base);
    for (int j4 = threadIdx.x; j4 < q; j4 += blockDim.x) {
        int r = base + (j4 << 2);
        if (r + 3 < n) {
            int4 L = lab4[j4];
            g_idx[atomicAdd(&cursor[L.x], 1)] = r;
            g_idx[atomicAdd(&cursor[L.y], 1)] = r + 1;
            g_idx[atomicAdd(&cursor[L.z], 1)] = r + 2;
            g_idx[atomicAdd(&cursor[L.w], 1)] = r + 3;
        } else {
            for (int k = 0; k < 4; k++)
                if (r + k < n) {
                    int c = labels[r + k];
                    g_idx[atomicAdd(&cursor[c], 1)] = r + k;
                }
        }
    }
}

// ---------------------------------------------------------------------------
// Kernel 5: per-class segment sum + EMA epilogue.
// 256 threads = 4 row-groups x 64 threads; each group covers a full row with
// 64 LDG.128s. 4 independent float4 accumulators (4 loads in flight/thread)
// and double-buffered index staging to overlap batches.
// ---------------------------------------------------------------------------
__global__ void __launch_bounds__(256, 8)
k_reduce(const float4* __restrict__ feats4,
         const float* __restrict__ protos,
         float* __restrict__ out) {
    int c   = blockIdx.x;
    int t   = threadIdx.x;
    int grp = t >> 6;     // 0..3: row group
    int col = t & 63;     // float4 column within the row
    int start = g_offset[c];
    int cnt   = g_count[c];

    __shared__ int sidx[2][256];
    float4 a0 = make_float4(0.f, 0.f, 0.f, 0.f);
    float4 a1 = make_float4(0.f, 0.f, 0.f, 0.f);
    float4 a2 = make_float4(0.f, 0.f, 0.f, 0.f);
    float4 a3 = make_float4(0.f, 0.f, 0.f, 0.f);

    // Preload first index batch.
    if (t < cnt) sidx[0][t] = g_idx[start + t];
    __syncthreads();

    int buf = 0;
    for (int base = 0; base < cnt; base += 256) {
        int m = min(256, cnt - base);
        // Prefetch next batch into the other buffer (no sync needed before
        // use of current buffer: it was synced at loop entry).
        int nb = base + 256;
        if (nb < cnt && t < cnt - nb) sidx[buf ^ 1][t] = g_idx[start + nb + t];

        const int* ix = sidx[buf];
        int j = grp;
        for (; j + 12 < m; j += 16) {
            long r0 = ix[j];
            long r1 = ix[j + 4];
            long r2 = ix[j + 8];
            long r3 = ix[j + 12];
            float4 v0 = feats4[r0 * (FEAT_DIM / 4) + col];
            float4 v1 = feats4[r1 * (FEAT_DIM / 4) + col];
            float4 v2 = feats4[r2 * (FEAT_DIM / 4) + col];
            float4 v3 = feats4[r3 * (FEAT_DIM / 4) + col];
            a0.x += v0.x; a0.y += v0.y; a0.z += v0.z; a0.w += v0.w;
            a1.x += v1.x; a1.y += v1.y; a1.z += v1.z; a1.w += v1.w;
            a2.x += v2.x; a2.y += v2.y; a2.z += v2.z; a2.w += v2.w;
            a3.x += v3.x; a3.y += v3.y; a3.z += v3.z; a3.w += v3.w;
        }
        for (; j < m; j += 4) {
            float4 v = feats4[(long)ix[j] * (FEAT_DIM / 4) + col];
            a0.x += v.x; a0.y += v.y; a0.z += v.z; a0.w += v.w;
        }
        __syncthreads();   // next buffer fully written; current buffer free
        buf ^= 1;
    }

    // Combine the 4 per-group partials.
    __shared__ float4 part4[4][64];   // 4 KB
    float4 a = make_float4((a0.x + a1.x) + (a2.x + a3.x),
                           (a0.y + a1.y) + (a2.y + a3.y),
                           (a0.z + a1.z) + (a2.z + a3.z),
                           (a0.w + a1.w) + (a2.w + a3.w));
    part4[grp][col] = a;
    __syncthreads();

    const float* part = (const float*)part4;   // part[g*256 + column]
    float sum = (part[0 * 256 + t] + part[1 * 256 + t])
              + (part[2 * 256 + t] + part[3 * 256 + t]);

    float p = protos[c * FEAT_DIM + t];
    float r = p;
    if (cnt > 0) {
        float mean = sum / (float)cnt;
        r = 0.9f * p + 0.1f * mean;
    }
    out[c * FEAT_DIM + t] = r;
}

// ---------------------------------------------------------------------------
// Launch
// ---------------------------------------------------------------------------
extern "C" void kernel_launch(void* const* d_in, const int* in_sizes, int n_in,
                              void* d_out, int out_size) {
    const float* features   = (const float*)d_in[0];
    const int*   labels     = (const int*)d_in[1];
    const float* prototypes = (const float*)d_in[2];
    float*       out        = (float*)d_out;

    int n = in_sizes[1];
    // rows per block-chunk, multiple of 4 so int4 loads stay aligned
    int rpb = ((n + NBLK * 4 - 1) / (NBLK * 4)) * 4;

    k_hist   <<<NBLK, 256>>>(labels, n, rpb);
    k_scanA  <<<NUM_CLASSES, NBLK>>>();
    k_scanB  <<<1, 1024>>>();
    k_scatter<<<NBLK, 256>>>(labels, n, rpb);
    k_reduce <<<NUM_CLASSES, 256>>>((const float4*)features, prototypes, out);
}

// round 7
// speedup vs baseline: 1.0437x; 1.0437x over previous
#include <cuda_runtime.h>
#include <cstdint>

#define NUM_CLASSES 1000
#define FEAT_DIM    256
#define NROWS       262144
#define NBLK        256          // chunks for hierarchical counting sort

#define NSTAGE      3            // pipeline stages in the reduce
#define RPS         8            // rows per stage (8 KB)
#define ROW_BYTES   1024         // FEAT_DIM * 4

// Device-global scratch (no allocation allowed in kernel_launch).
__device__ int g_hist[NBLK * NUM_CLASSES];
__device__ int g_count[NUM_CLASSES];
__device__ int g_offset[NUM_CLASSES];
__device__ int g_idx[NROWS];

// ---------------------------------------------------------------------------
// mbarrier / bulk-async helpers
// ---------------------------------------------------------------------------
__device__ __forceinline__ uint32_t s2u(const void* p) {
    return (uint32_t)__cvta_generic_to_shared(p);
}
__device__ __forceinline__ void mbar_init(uint32_t a, uint32_t cnt) {
    asm volatile("mbarrier.init.shared.b64 [%0], %1;" :: "r"(a), "r"(cnt) : "memory");
}
__device__ __forceinline__ void mbar_expect_tx(uint32_t a, uint32_t bytes) {
    asm volatile("mbarrier.arrive.expect_tx.shared.b64 _, [%0], %1;"
                 :: "r"(a), "r"(bytes) : "memory");
}
__device__ __forceinline__ void mbar_arrive(uint32_t a) {
    asm volatile("mbarrier.arrive.shared.b64 _, [%0];" :: "r"(a) : "memory");
}
__device__ __forceinline__ void mbar_wait(uint32_t a, uint32_t parity) {
    asm volatile(
        "{\n\t.reg .pred P;\n"
        "WL%=:\n\t"
        "mbarrier.try_wait.parity.acquire.cta.shared::cta.b64 P, [%0], %1;\n\t"
        "@P bra WD%=;\n\t"
        "bra WL%=;\n"
        "WD%=:\n\t}"
        :: "r"(a), "r"(parity) : "memory");
}
__device__ __forceinline__ void bulk_ld(uint32_t dst, const void* src,
                                        uint32_t bytes, uint32_t mbar) {
    asm volatile(
        "cp.async.bulk.shared::cta.global.mbarrier::complete_tx::bytes "
        "[%0], [%1], %2, [%3];"
        :: "r"(dst), "l"(src), "r"(bytes), "r"(mbar) : "memory");
}

// ---------------------------------------------------------------------------
// Kernel 1: per-block label histogram (smem privatized, int4 label loads)
// ---------------------------------------------------------------------------
__global__ void k_hist(const int* __restrict__ labels, int n, int rpb) {
    __shared__ int h[NUM_CLASSES];
    for (int i = threadIdx.x; i < NUM_CLASSES; i += blockDim.x) h[i] = 0;
    __syncthreads();
    int base = blockIdx.x * rpb;
    int q    = rpb >> 2;
    const int4* lab4 = (const int4*)(labels + base);   // base % 4 == 0
    for (int j4 = threadIdx.x; j4 < q; j4 += blockDim.x) {
        int r = base + (j4 << 2);
        if (r + 3 < n) {
            int4 L = lab4[j4];
            atomicAdd(&h[L.x], 1);
            atomicAdd(&h[L.y], 1);
            atomicAdd(&h[L.z], 1);
            atomicAdd(&h[L.w], 1);
        } else {
            for (int k = 0; k < 4; k++)
                if (r + k < n) atomicAdd(&h[labels[r + k]], 1);
        }
    }
    __syncthreads();
    int* dst = &g_hist[blockIdx.x * NUM_CLASSES];
    for (int i = threadIdx.x; i < NUM_CLASSES; i += blockDim.x) dst[i] = h[i];
}

// ---------------------------------------------------------------------------
// Kernel 2: per-class exclusive scan across the NBLK block-chunks.
// ---------------------------------------------------------------------------
__global__ void k_scanA() {
    int c = blockIdx.x;
    int t = threadIdx.x;
    int v = g_hist[t * NUM_CLASSES + c];

    int lane = t & 31, w = t >> 5;
    int x = v;
    #pragma unroll
    for (int o = 1; o < 32; o <<= 1) {
        int y = __shfl_up_sync(0xffffffffu, x, o);
        if (lane >= o) x += y;
    }
    __shared__ int wt[NBLK / 32];
    if (lane == 31) wt[w] = x;
    __syncthreads();
    if (t == 0) {
        int s = 0;
        #pragma unroll
        for (int i = 0; i < NBLK / 32; i++) { int tmp = wt[i]; wt[i] = s; s += tmp; }
    }
    __syncthreads();
    int incl = x + wt[w];
    g_hist[t * NUM_CLASSES + c] = incl - v;   // exclusive prefix within class
    if (t == NBLK - 1) g_count[c] = incl;     // class total
}

// ---------------------------------------------------------------------------
// Kernel 3: exclusive scan over 1000 class totals (single block)
// ---------------------------------------------------------------------------
__global__ void k_scanB() {
    __shared__ int s[1024];
    int t = threadIdx.x;
    s[t] = (t < NUM_CLASSES) ? g_count[t] : 0;
    for (int off = 1; off < 1024; off <<= 1) {
        __syncthreads();
        int v = (t >= off) ? s[t - off] : 0;
        __syncthreads();
        s[t] += v;
    }
    __syncthreads();
    if (t < NUM_CLASSES) g_offset[t] = (t == 0) ? 0 : s[t - 1];
}

// ---------------------------------------------------------------------------
// Kernel 4: scatter row indices; smem cursors only, int4 label loads.
// ---------------------------------------------------------------------------
__global__ void k_scatter(const int* __restrict__ labels, int n, int rpb) {
    __shared__ int cursor[NUM_CLASSES];
    int b = blockIdx.x;
    const int* pre = &g_hist[b * NUM_CLASSES];
    for (int c = threadIdx.x; c < NUM_CLASSES; c += blockDim.x)
        cursor[c] = g_offset[c] + pre[c];
    __syncthreads();
    int base = b * rpb;
    int q    = rpb >> 2;
    const int4* lab4 = (const int4*)(labels + base);
    for (int j4 = threadIdx.x; j4 < q; j4 += blockDim.x) {
        int r = base + (j4 << 2);
        if (r + 3 < n) {
            int4 L = lab4[j4];
            g_idx[atomicAdd(&cursor[L.x], 1)] = r;
            g_idx[atomicAdd(&cursor[L.y], 1)] = r + 1;
            g_idx[atomicAdd(&cursor[L.z], 1)] = r + 2;
            g_idx[atomicAdd(&cursor[L.w], 1)] = r + 3;
        } else {
            for (int k = 0; k < 4; k++)
                if (r + k < n) {
                    int c = labels[r + k];
                    g_idx[atomicAdd(&cursor[c], 1)] = r + k;
                }
        }
    }
}

// ---------------------------------------------------------------------------
// Kernel 5: warp-specialized pipelined reduce.
// 288 threads = 8 consumer warps (256 thr) + 1 producer warp.
// Producer: reads class row-indices coalesced, issues cp.async.bulk (1KB/row,
// 8 rows/stage, 3 stages) with mbarrier complete_tx. In-flight bytes are
// decoupled from warp scoreboards -> deep DRAM pipelining.
// Consumers: wait full[s]; thread (grp,col) adds rows grp and grp+4 of the
// stage (2 conflict-free LDS.128 + FADDs); per-warp arrive on empty[s].
// ---------------------------------------------------------------------------
__global__ void __launch_bounds__(288, 7)
k_reduce(const char* __restrict__ featsB,
         const float* __restrict__ protos,
         float* __restrict__ out) {
    __shared__ float4 stage[NSTAGE][RPS * 64];          // 3 x 8KB
    __shared__ float4 part4[4][64];                     // 4KB combine buffer
    __shared__ alignas(8) unsigned long long mbar[2 * NSTAGE]; // full/empty pairs

    int c = blockIdx.x;
    int t = threadIdx.x;
    int start = g_offset[c];
    int cnt   = g_count[c];
    int nIter = (cnt + RPS - 1) / RPS;

    if (t == 0) {
        #pragma unroll
        for (int s = 0; s < NSTAGE; s++) {
            mbar_init(s2u(&mbar[2 * s]), 1);        // full: tx-completion
            mbar_init(s2u(&mbar[2 * s + 1]), 8);    // empty: 8 consumer warps
        }
    }
    __syncthreads();

    if (t >= 256) {
        // ---- producer warp ----
        int lane = t - 256;
        int idxReg = 0;
        int s = 0, wrap = 0;
        for (int i = 0; i < nIter; i++) {
            if ((i & 3) == 0) {           // refill 32 indices (4 iterations worth)
                int p = i * RPS + lane;
                idxReg = (p < cnt) ? g_idx[start + p] : 0;
            }
            if (wrap > 0)
                mbar_wait(s2u(&mbar[2 * s + 1]), (unsigned)((wrap - 1) & 1));
            int m = min(RPS, cnt - i * RPS);
            int row = __shfl_sync(0xffffffffu, idxReg, ((i & 3) << 3) + (lane & 7));
            if (lane == 0)
                mbar_expect_tx(s2u(&mbar[2 * s]), (uint32_t)m * ROW_BYTES);
            __syncwarp();
            if (lane < m)
                bulk_ld(s2u(&stage[s][0]) + (uint32_t)lane * ROW_BYTES,
                        featsB + (long)row * ROW_BYTES,
                        ROW_BYTES, s2u(&mbar[2 * s]));
            if (++s == NSTAGE) { s = 0; wrap++; }
        }
    } else {
        // ---- consumer warps ----
        int grp = t >> 6;     // 0..3
        int col = t & 63;
        float4 a0 = make_float4(0.f, 0.f, 0.f, 0.f);
        float4 a1 = make_float4(0.f, 0.f, 0.f, 0.f);
        int s = 0, ph = 0;
        for (int i = 0; i < nIter; i++) {
            mbar_wait(s2u(&mbar[2 * s]), (unsigned)ph);
            int m = min(RPS, cnt - i * RPS);
            if (grp < m) {
                float4 v = stage[s][grp * 64 + col];
                a0.x += v.x; a0.y += v.y; a0.z += v.z; a0.w += v.w;
            }
            if (grp + 4 < m) {
                float4 v = stage[s][(grp + 4) * 64 + col];
                a1.x += v.x; a1.y += v.y; a1.z += v.z; a1.w += v.w;
            }
            __syncwarp();
            if ((t & 31) == 0) mbar_arrive(s2u(&mbar[2 * s + 1]));
            if (++s == NSTAGE) { s = 0; ph ^= 1; }
        }
        float4 a = make_float4(a0.x + a1.x, a0.y + a1.y,
                               a0.z + a1.z, a0.w + a1.w);
        part4[grp][col] = a;
    }

    __syncthreads();

    if (t < 256) {
        const float* part = (const float*)part4;   // part[g*256 + column]
        float sum = (part[0 * 256 + t] + part[1 * 256 + t])
                  + (part[2 * 256 + t] + part[3 * 256 + t]);
        float p = protos[c * FEAT_DIM + t];
        float r = p;
        if (cnt > 0) {
            float mean = sum / (float)cnt;
            r = 0.9f * p + 0.1f * mean;
        }
        out[c * FEAT_DIM + t] = r;
    }
}

// ---------------------------------------------------------------------------
// Launch
// ---------------------------------------------------------------------------
extern "C" void kernel_launch(void* const* d_in, const int* in_sizes, int n_in,
                              void* d_out, int out_size) {
    const float* features   = (const float*)d_in[0];
    const int*   labels     = (const int*)d_in[1];
    const float* prototypes = (const float*)d_in[2];
    float*       out        = (float*)d_out;

    int n = in_sizes[1];
    // rows per block-chunk, multiple of 4 so int4 loads stay aligned
    int rpb = ((n + NBLK * 4 - 1) / (NBLK * 4)) * 4;

    k_hist   <<<NBLK, 256>>>(labels, n, rpb);
    k_scanA  <<<NUM_CLASSES, NBLK>>>();
    k_scanB  <<<1, 1024>>>();
    k_scatter<<<NBLK, 256>>>(labels, n, rpb);
    k_reduce <<<NUM_CLASSES, 288>>>((const char*)features, prototypes, out);
}

// round 8
// speedup vs baseline: 1.0682x; 1.0234x over previous
#include <cuda_runtime.h>
#include <cstdint>

#define NUM_CLASSES 1000
#define FEAT_DIM    256
#define NROWS       262144
#define NBLK        256          // chunks for hierarchical counting sort

#define NSTAGE      3            // pipeline stages in the reduce
#define RPS         8            // rows per stage (8 KB)
#define ROW_BYTES   1024         // FEAT_DIM * 4

// Device-global scratch (no allocation allowed in kernel_launch).
__device__ alignas(16) int g_hist[NBLK * NUM_CLASSES];
__device__ alignas(16) int g_count[NUM_CLASSES];
__device__ alignas(16) int g_offset[NUM_CLASSES];
__device__ int g_idx[NROWS];

// ---------------------------------------------------------------------------
// mbarrier / bulk-async helpers
// ---------------------------------------------------------------------------
__device__ __forceinline__ uint32_t s2u(const void* p) {
    return (uint32_t)__cvta_generic_to_shared(p);
}
__device__ __forceinline__ void mbar_init(uint32_t a, uint32_t cnt) {
    asm volatile("mbarrier.init.shared.b64 [%0], %1;" :: "r"(a), "r"(cnt) : "memory");
}
__device__ __forceinline__ void mbar_expect_tx(uint32_t a, uint32_t bytes) {
    asm volatile("mbarrier.arrive.expect_tx.shared.b64 _, [%0], %1;"
                 :: "r"(a), "r"(bytes) : "memory");
}
__device__ __forceinline__ void mbar_arrive(uint32_t a) {
    asm volatile("mbarrier.arrive.shared.b64 _, [%0];" :: "r"(a) : "memory");
}
__device__ __forceinline__ void mbar_wait(uint32_t a, uint32_t parity) {
    asm volatile(
        "{\n\t.reg .pred P;\n"
        "WL%=:\n\t"
        "mbarrier.try_wait.parity.acquire.cta.shared::cta.b64 P, [%0], %1;\n\t"
        "@P bra WD%=;\n\t"
        "bra WL%=;\n"
        "WD%=:\n\t}"
        :: "r"(a), "r"(parity) : "memory");
}
__device__ __forceinline__ void bulk_ld(uint32_t dst, const void* src,
                                        uint32_t bytes, uint32_t mbar) {
    asm volatile(
        "cp.async.bulk.shared::cta.global.mbarrier::complete_tx::bytes "
        "[%0], [%1], %2, [%3];"
        :: "r"(dst), "l"(src), "r"(bytes), "r"(mbar) : "memory");
}

// ---------------------------------------------------------------------------
// Kernel 1: per-block label histogram. 1024 threads, one row per thread:
// shortest possible dependent chain, max warps for latency hiding.
// ---------------------------------------------------------------------------
__global__ void __launch_bounds__(1024)
k_hist(const int* __restrict__ labels, int n, int rpb) {
    __shared__ int h[NUM_CLASSES];
    int t = threadIdx.x;
    for (int i = t; i < NUM_CLASSES; i += 1024) h[i] = 0;
    __syncthreads();
    int base = blockIdx.x * rpb;
    for (int j = t; j < rpb; j += 1024) {
        int r = base + j;
        if (r < n) atomicAdd(&h[labels[r]], 1);
    }
    __syncthreads();
    int* dst = &g_hist[blockIdx.x * NUM_CLASSES];
    for (int i = t; i < NUM_CLASSES; i += 1024) dst[i] = h[i];
}

// ---------------------------------------------------------------------------
// Kernel 2: per-class exclusive scan across the NBLK block-chunks.
// ---------------------------------------------------------------------------
__global__ void k_scanA() {
    int c = blockIdx.x;
    int t = threadIdx.x;
    int v = g_hist[t * NUM_CLASSES + c];

    int lane = t & 31, w = t >> 5;
    int x = v;
    #pragma unroll
    for (int o = 1; o < 32; o <<= 1) {
        int y = __shfl_up_sync(0xffffffffu, x, o);
        if (lane >= o) x += y;
    }
    __shared__ int wt[NBLK / 32];
    if (lane == 31) wt[w] = x;
    __syncthreads();
    if (t == 0) {
        int s = 0;
        #pragma unroll
        for (int i = 0; i < NBLK / 32; i++) { int tmp = wt[i]; wt[i] = s; s += tmp; }
    }
    __syncthreads();
    int incl = x + wt[w];
    g_hist[t * NUM_CLASSES + c] = incl - v;   // exclusive prefix within class
    if (t == NBLK - 1) g_count[c] = incl;     // class total
}

// ---------------------------------------------------------------------------
// Kernel 3: exclusive scan over 1000 class totals (single block)
// ---------------------------------------------------------------------------
__global__ void k_scanB() {
    __shared__ int s[1024];
    int t = threadIdx.x;
    s[t] = (t < NUM_CLASSES) ? g_count[t] : 0;
    for (int off = 1; off < 1024; off <<= 1) {
        __syncthreads();
        int v = (t >= off) ? s[t - off] : 0;
        __syncthreads();
        s[t] += v;
    }
    __syncthreads();
    if (t < NUM_CLASSES) g_offset[t] = (t == 0) ? 0 : s[t - 1];
}

// ---------------------------------------------------------------------------
// Kernel 4: scatter. 1024 threads, one row per thread: chain is just
// LDG(label) -> ATOMS(cursor) -> STG(g_idx), hidden by ~55 warps/SM.
// ---------------------------------------------------------------------------
__global__ void __launch_bounds__(1024)
k_scatter(const int* __restrict__ labels, int n, int rpb) {
    __shared__ int cursor[NUM_CLASSES];
    int b = blockIdx.x;
    int t = threadIdx.x;
    const int* pre = &g_hist[b * NUM_CLASSES];
    for (int i = t; i < NUM_CLASSES; i += 1024)
        cursor[i] = g_offset[i] + pre[i];
    __syncthreads();
    int base = b * rpb;
    for (int j = t; j < rpb; j += 1024) {
        int r = base + j;
        if (r < n) {
            int c = labels[r];
            g_idx[atomicAdd(&cursor[c], 1)] = r;
        }
    }
}

// ---------------------------------------------------------------------------
// Kernel 5: warp-specialized pipelined reduce (unchanged from round 7).
// 288 threads = 8 consumer warps (256 thr) + 1 producer warp.
// ---------------------------------------------------------------------------
__global__ void __launch_bounds__(288, 7)
k_reduce(const char* __restrict__ featsB,
         const float* __restrict__ protos,
         float* __restrict__ out) {
    __shared__ float4 stage[NSTAGE][RPS * 64];          // 3 x 8KB
    __shared__ float4 part4[4][64];                     // 4KB combine buffer
    __shared__ alignas(8) unsigned long long mbar[2 * NSTAGE]; // full/empty pairs

    int c = blockIdx.x;
    int t = threadIdx.x;
    int start = g_offset[c];
    int cnt   = g_count[c];
    int nIter = (cnt + RPS - 1) / RPS;

    if (t == 0) {
        #pragma unroll
        for (int s = 0; s < NSTAGE; s++) {
            mbar_init(s2u(&mbar[2 * s]), 1);        // full: tx-completion
            mbar_init(s2u(&mbar[2 * s + 1]), 8);    // empty: 8 consumer warps
        }
    }
    __syncthreads();

    if (t >= 256) {
        // ---- producer warp ----
        int lane = t - 256;
        int idxReg = 0;
        int s = 0, wrap = 0;
        for (int i = 0; i < nIter; i++) {
            if ((i & 3) == 0) {           // refill 32 indices (4 iterations worth)
                int p = i * RPS + lane;
                idxReg = (p < cnt) ? g_idx[start + p] : 0;
            }
            if (wrap > 0)
                mbar_wait(s2u(&mbar[2 * s + 1]), (unsigned)((wrap - 1) & 1));
            int m = min(RPS, cnt - i * RPS);
            int row = __shfl_sync(0xffffffffu, idxReg, ((i & 3) << 3) + (lane & 7));
            if (lane == 0)
                mbar_expect_tx(s2u(&mbar[2 * s]), (uint32_t)m * ROW_BYTES);
            __syncwarp();
            if (lane < m)
                bulk_ld(s2u(&stage[s][0]) + (uint32_t)lane * ROW_BYTES,
                        featsB + (long)row * ROW_BYTES,
                        ROW_BYTES, s2u(&mbar[2 * s]));
            if (++s == NSTAGE) { s = 0; wrap++; }
        }
    } else {
        // ---- consumer warps ----
        int grp = t >> 6;     // 0..3
        int col = t & 63;
        float4 a0 = make_float4(0.f, 0.f, 0.f, 0.f);
        float4 a1 = make_float4(0.f, 0.f, 0.f, 0.f);
        int s = 0, ph = 0;
        for (int i = 0; i < nIter; i++) {
            mbar_wait(s2u(&mbar[2 * s]), (unsigned)ph);
            int m = min(RPS, cnt - i * RPS);
            if (grp < m) {
                float4 v = stage[s][grp * 64 + col];
                a0.x += v.x; a0.y += v.y; a0.z += v.z; a0.w += v.w;
            }
            if (grp + 4 < m) {
                float4 v = stage[s][(grp + 4) * 64 + col];
                a1.x += v.x; a1.y += v.y; a1.z += v.z; a1.w += v.w;
            }
            __syncwarp();
            if ((t & 31) == 0) mbar_arrive(s2u(&mbar[2 * s + 1]));
            if (++s == NSTAGE) { s = 0; ph ^= 1; }
        }
        float4 a = make_float4(a0.x + a1.x, a0.y + a1.y,
                               a0.z + a1.z, a0.w + a1.w);
        part4[grp][col] = a;
    }

    __syncthreads();

    if (t < 256) {
        const float* part = (const float*)part4;   // part[g*256 + column]
        float sum = (part[0 * 256 + t] + part[1 * 256 + t])
                  + (part[2 * 256 + t] + part[3 * 256 + t]);
        float p = protos[c * FEAT_DIM + t];
        float r = p;
        if (cnt > 0) {
            float mean = sum / (float)cnt;
            r = 0.9f * p + 0.1f * mean;
        }
        out[c * FEAT_DIM + t] = r;
    }
}

// ---------------------------------------------------------------------------
// Launch
// ---------------------------------------------------------------------------
extern "C" void kernel_launch(void* const* d_in, const int* in_sizes, int n_in,
                              void* d_out, int out_size) {
    const float* features   = (const float*)d_in[0];
    const int*   labels     = (const int*)d_in[1];
    const float* prototypes = (const float*)d_in[2];
    float*       out        = (float*)d_out;

    int n = in_sizes[1];
    int rpb = ((n + NBLK - 1) / NBLK + 3) & ~3;   // rows per block-chunk

    k_hist   <<<NBLK, 1024>>>(labels, n, rpb);
    k_scanA  <<<NUM_CLASSES, NBLK>>>();
    k_scanB  <<<1, 1024>>>();
    k_scatter<<<NBLK, 1024>>>(labels, n, rpb);
    k_reduce <<<NUM_CLASSES, 288>>>((const char*)features, prototypes, out);
}